// round 13
// baseline (speedup 1.0000x reference)
#include <cuda_runtime.h>

#define NB 8
#define NK 9
#define NA 36864
#define NG 128
#define BA (NB*NA)
#define IT 36            // NA / 1024 anchors per thread in k_sample
#define LISTCAP 512

struct Keys { unsigned k[32]; }; // per image b: [4b]=k1.lo0,[4b+1]=k1.lo1,[4b+2]=k2.lo0,[4b+3]=k2.lo1

// ------------- scratch: static device globals (no allocation) -------------
__device__ float              g_maxiou[BA];
__device__ int                g_mgt[BA];
__device__ unsigned           g_sp[BA];
__device__ unsigned           g_sn[BA];
__device__ unsigned long long g_colmax[NB * NG];
__device__ float              g_loss[NB * 2];

// ------------- threefry2x32, bit-exact JAX replica -------------
__host__ __device__ __forceinline__ void tf2x32(unsigned k0, unsigned k1,
                                                unsigned x0, unsigned x1,
                                                unsigned &o0, unsigned &o1) {
  unsigned k2 = k0 ^ k1 ^ 0x1BD11BDAu;
  x0 += k0; x1 += k1;
#define TFR(r) { x0 += x1; x1 = (x1 << (r)) | (x1 >> (32 - (r))); x1 ^= x0; }
  TFR(13) TFR(15) TFR(26) TFR(6)
  x0 += k1; x1 += k2 + 1u;
  TFR(17) TFR(29) TFR(16) TFR(24)
  x0 += k2; x1 += k0 + 2u;
  TFR(13) TFR(15) TFR(26) TFR(6)
  x0 += k0; x1 += k1 + 3u;
  TFR(17) TFR(29) TFR(16) TFR(24)
  x0 += k1; x1 += k2 + 4u;
  TFR(13) TFR(15) TFR(26) TFR(6)
  x0 += k2; x1 += k0 + 5u;
#undef TFR
  o0 = x0; o1 = x1;
}

// ------------- IoU in XLA's exact op order (no FMA contraction) -------------
__device__ __forceinline__ float iou_fn(float4 A, float aa, float4 G) {
  float ltx = fmaxf(A.x, G.x), lty = fmaxf(A.y, G.y);
  float rbx = fminf(A.z, G.z), rby = fminf(A.w, G.w);
  float wx = fmaxf(__fsub_rn(rbx, ltx), 0.0f);
  float wy = fmaxf(__fsub_rn(rby, lty), 0.0f);
  float inter = __fmul_rn(wx, wy);
  float ag = __fmul_rn(__fsub_rn(G.z, G.x), __fsub_rn(G.w, G.y));
  float den = __fadd_rn(__fsub_rn(__fadd_rn(aa, ag), inter), 1e-6f);
  return __fdiv_rn(inter, den);
}

// ------------- K1: per-anchor row max/argmax + priority streams -------------
__global__ void __launch_bounds__(256) k_row(const float* __restrict__ anchors,
                                             const float* __restrict__ gt, Keys keys) {
  int b = blockIdx.y;
  int a = blockIdx.x * 256 + threadIdx.x;
  __shared__ float4 sg[NG];
  if (threadIdx.x < NG)
    sg[threadIdx.x] = reinterpret_cast<const float4*>(gt)[b * NG + threadIdx.x];
  if (blockIdx.x == 0 && threadIdx.x < NG)
    g_colmax[b * NG + threadIdx.x] = 0ull;
  __syncthreads();
  float4 A = reinterpret_cast<const float4*>(anchors)[a];
  float aa = __fmul_rn(__fsub_rn(A.z, A.x), __fsub_rn(A.w, A.y));
  float best = -1.0f; int bi = 0;
#pragma unroll 4
  for (int g = 0; g < NG; ++g) {
    float v = iou_fn(A, aa, sg[g]);
    if (v > best) { best = v; bi = g; }        // first-max == jnp.argmax
  }
  int off = b * NA + a;
  g_maxiou[off] = best;
  g_mgt[off] = bi;
  unsigned o0, o1;
  tf2x32(keys.k[4 * b + 0], keys.k[4 * b + 1], 0u, (unsigned)a, o0, o1);
  g_sp[off] = (o0 ^ o1) >> 9;                  // 23-bit uniform-order priority
  tf2x32(keys.k[4 * b + 2], keys.k[4 * b + 3], 0u, (unsigned)a, o0, o1);
  g_sn[off] = (o0 ^ o1) >> 9;
}

// ------------- K2: per-gt column argmax (packed u64 atomicMax) -------------
__global__ void __launch_bounds__(256) k_col(const float* __restrict__ anchors,
                                             const float* __restrict__ gt) {
  int b = blockIdx.y;
  int g0 = blockIdx.x * 8;
  int a0 = blockIdx.z * 9216;
  __shared__ float4 sg[8];
  if (threadIdx.x < 8)
    sg[threadIdx.x] = reinterpret_cast<const float4*>(gt)[b * NG + g0 + threadIdx.x];
  __syncthreads();
  unsigned long long best[8] = {0, 0, 0, 0, 0, 0, 0, 0};
  for (int i = 0; i < 36; ++i) {
    int a = a0 + i * 256 + threadIdx.x;
    float4 A = reinterpret_cast<const float4*>(anchors)[a];
    float aa = __fmul_rn(__fsub_rn(A.z, A.x), __fsub_rn(A.w, A.y));
    unsigned long long inv = (unsigned long long)(0xFFFFFFFFu - (unsigned)a);
#pragma unroll
    for (int j = 0; j < 8; ++j) {
      float v = iou_fn(A, aa, sg[j]);
      unsigned long long key = ((unsigned long long)__float_as_uint(v) << 32) | inv;
      if (key > best[j]) best[j] = key;        // max iou; tie -> smallest anchor idx
    }
  }
  __shared__ unsigned long long red[8][8];
#pragma unroll
  for (int j = 0; j < 8; ++j) {
    unsigned long long v = best[j];
    for (int o = 16; o; o >>= 1) {
      unsigned long long t = __shfl_down_sync(0xffffffffu, v, o);
      if (t > v) v = t;
    }
    if ((threadIdx.x & 31) == 0) red[j][threadIdx.x >> 5] = v;
  }
  __syncthreads();
  if (threadIdx.x < 8) {
    int j = threadIdx.x;
    unsigned long long v = red[j][0];
#pragma unroll
    for (int w = 1; w < 8; ++w) if (red[j][w] > v) v = red[j][w];
    atomicMax(&g_colmax[b * NG + g0 + j], v);
  }
}

// ------------- block reductions (1024 threads) -------------
__device__ __forceinline__ int blkSumI(int v, int* sred) {
  int l = threadIdx.x & 31, w = threadIdx.x >> 5;
  for (int o = 16; o; o >>= 1) v += __shfl_down_sync(0xffffffffu, v, o);
  if (l == 0) sred[w] = v;
  __syncthreads();
  if (w == 0) {
    int t = sred[l];
    for (int o = 16; o; o >>= 1) t += __shfl_down_sync(0xffffffffu, t, o);
    if (l == 0) sred[0] = t;
  }
  __syncthreads();
  int r = sred[0];
  __syncthreads();
  return r;
}

__device__ __forceinline__ float blkSumF(float v, float* sred) {
  int l = threadIdx.x & 31, w = threadIdx.x >> 5;
  for (int o = 16; o; o >>= 1) v += __shfl_down_sync(0xffffffffu, v, o);
  if (l == 0) sred[w] = v;
  __syncthreads();
  if (w == 0) {
    float t = sred[l];
    for (int o = 16; o; o >>= 1) t += __shfl_down_sync(0xffffffffu, t, o);
    if (l == 0) sred[0] = t;
  }
  __syncthreads();
  float r = sred[0];
  __syncthreads();
  return r;
}

// ------------- exact top-k selection with stable-argsort tie semantics -------------
// NOTE: `list` ALIASES `hist` (the histogram is dead once sScal[0..1] are set),
// keeping dynamic shared at 45056 B (< 48 KB default cap, no attribute opt-in).
__device__ void selectTopK(signed char* lab, unsigned* hist,
                           const unsigned* __restrict__ prio, int b, int k, int count,
                           int want, unsigned* warpSum, int* sScal) {
  int tid = threadIdx.x;
  unsigned long long* list = (unsigned long long*)hist;   // alias, used after hist is dead
  if (k >= count) return;                       // keep all masked
  if (k <= 0) {                                 // demote all masked
    for (int i = 0; i < IT; ++i) {
      int a = i * 1024 + tid;
      if (lab[a] == want) lab[a] = -1;
    }
    __syncthreads();
    return;
  }
  // pass 1: histogram over top 11 bits of the 23-bit priority
  for (int j = tid; j < 2048; j += 1024) hist[j] = 0u;
  if (tid == 0) sScal[2] = 0;
  __syncthreads();
  for (int i = 0; i < IT; ++i) {
    int a = i * 1024 + tid;
    if (lab[a] == want) atomicAdd(&hist[prio[b * NA + a] >> 12], 1u);
  }
  __syncthreads();
  {
    int w = tid >> 5, l = tid & 31;
    unsigned s = hist[w * 64 + l] + hist[w * 64 + l + 32];
    for (int o = 16; o; o >>= 1) s += __shfl_down_sync(0xffffffffu, s, o);
    if (l == 0) warpSum[w] = s;
  }
  __syncthreads();
  if (tid == 0) {
    int acc = 0, C = 0;
    for (int w = 31; w >= 0; --w) {
      if (acc + (int)warpSum[w] >= k) { C = w; break; }
      acc += (int)warpSum[w];
    }
    int B = C * 64;
    for (int bin = C * 64 + 63; bin >= C * 64; --bin) {
      if (acc + (int)hist[bin] >= k) { B = bin; break; }
      acc += (int)hist[bin];
    }
    sScal[0] = B; sScal[1] = acc;               // acc = count strictly above bucket B
  }
  __syncthreads();
  int B = sScal[0], above = sScal[1], r = k - above;  // 1 <= r <= hist[B]
  // hist is dead from here on; list overwrites it.
  for (int i = 0; i < IT; ++i) {
    int a = i * 1024 + tid;
    if (lab[a] == want) {
      unsigned p = prio[b * NA + a];
      int bkt = (int)(p >> 12);
      if (bkt < B) {
        lab[a] = -1;                            // below threshold bucket: demote
      } else if (bkt == B) {
        int pos = atomicAdd(&sScal[2], 1);
        if (pos < LISTCAP)
          list[pos] = ((unsigned long long)p << 32) |
                      (unsigned long long)(0xFFFFFFFFu - (unsigned)a);
      }
    }
  }
  __syncthreads();
  int m = sScal[2]; if (m > LISTCAP) m = LISTCAP;
  for (int e = tid; e < m; e += 1024) {
    unsigned long long K = list[e];
    int rank = 0;
    for (int j = 0; j < m; ++j) rank += (list[j] > K);  // value desc, index asc (keys unique)
    if (rank >= r) {
      unsigned a = 0xFFFFFFFFu - (unsigned)(K & 0xFFFFFFFFull);
      lab[a] = -1;
    }
  }
  __syncthreads();
}

// ------------- K3: per-image labels, sampling, losses -------------
// dynamic shared: lab 36864 B + hist 8192 B = 45056 B (< 48 KB, no opt-in needed)
__global__ void __launch_bounds__(1024) k_sample(const float* __restrict__ cls,
                                                 const float* __restrict__ boxp,
                                                 const float* __restrict__ anchors,
                                                 const float* __restrict__ gt) {
  extern __shared__ unsigned char smem[];
  signed char* lab = (signed char*)smem;                                // 36864 B
  unsigned* hist = (unsigned*)(smem + NA);                              // 8192 B (list aliases)
  __shared__ int sredI[32];
  __shared__ float sredF[32];
  __shared__ unsigned warpSum[32];
  __shared__ int sScal[3];
  int b = blockIdx.x, tid = threadIdx.x;

  // base labels
  for (int i = 0; i < IT; ++i) {
    int a = i * 1024 + tid;
    float mi = g_maxiou[b * NA + a];
    lab[a] = (mi >= 0.7f) ? 1 : ((mi < 0.3f) ? 0 : -1);
  }
  __syncthreads();
  // forced positives (best anchor per gt)
  if (tid < NG) {
    unsigned long long key = g_colmax[b * NG + tid];
    unsigned a = 0xFFFFFFFFu - (unsigned)(key & 0xFFFFFFFFull);
    lab[a] = 1;
  }
  __syncthreads();

  int myPos = 0, myNeg = 0;
  for (int i = 0; i < IT; ++i) {
    int l = lab[i * 1024 + tid];
    myPos += (l == 1); myNeg += (l == 0);
  }
  int numPos = blkSumI(myPos, sredI);
  int numNeg = blkSumI(myNeg, sredI);
  int targetPos = min(128, numPos);
  selectTopK(lab, hist, g_sp, b, targetPos, numPos, 1, warpSum, sScal);
  int targetNeg = min(256 - targetPos, numNeg);
  selectTopK(lab, hist, g_sn, b, targetNeg, numNeg, 0, warpSum, sScal);

  // losses over sampled (<=256) anchors
  float clsSum = 0.f, boxSum = 0.f;
  int vcnt = 0, pcnt = 0;
  for (int i = 0; i < IT; ++i) {
    int a = i * 1024 + tid;
    int l = lab[a];
    if (l >= 0) {
      int j = a % NK, pix = a / NK;
      float x = cls[(b * NK + j) * 4096 + pix];
      float bce = fmaxf(x, 0.f) + log1pf(expf(-fabsf(x)));
      if (l == 1) bce -= x;
      clsSum += bce; ++vcnt;
      if (l == 1) {
        ++pcnt;
        int g = g_mgt[b * NA + a];
        float4 A = reinterpret_cast<const float4*>(anchors)[a];
        float4 G = reinterpret_cast<const float4*>(gt)[b * NG + g];
        float aw = A.z - A.x, ah = A.w - A.y;
        float acx = (A.x + A.z) * 0.5f, acy = (A.y + A.w) * 0.5f;
        float gw = G.z - G.x, gh = G.w - G.y;
        float gcx = (G.x + G.z) * 0.5f, gcy = (G.y + G.w) * 0.5f;
        float t[4] = {(gcx - acx) / aw, (gcy - acy) / ah, logf(gw / aw), logf(gh / ah)};
        int base = (b * 36 + 4 * j) * 4096 + pix;
#pragma unroll
        for (int c = 0; c < 4; ++c) {
          float d = boxp[base + c * 4096] - t[c];
          float ad = fabsf(d);
          boxSum += (ad < 1.f) ? 0.5f * d * d : ad - 0.5f;
        }
      }
    }
  }
  clsSum = blkSumF(clsSum, sredF);
  vcnt = blkSumI(vcnt, sredI);
  boxSum = blkSumF(boxSum, sredF);
  pcnt = blkSumI(pcnt, sredI);
  if (tid == 0) {
    g_loss[b * 2] = clsSum / fmaxf((float)vcnt, 1.f);
    g_loss[b * 2 + 1] = boxSum / fmaxf(4.f * (float)pcnt, 1.f);
  }
}

// ------------- K4: means -------------
__global__ void k_final(float* __restrict__ out) {
  if (threadIdx.x == 0) {
    float cs = 0.f, bs = 0.f;
    for (int b = 0; b < NB; ++b) { cs += g_loss[2 * b]; bs += g_loss[2 * b + 1]; }
    cs *= 0.125f; bs *= 0.125f;
    out[0] = cs; out[1] = bs; out[2] = cs + bs;
  }
}

extern "C" void kernel_launch(void* const* d_in, const int* in_sizes, int n_in,
                              void* d_out, int out_size) {
  (void)out_size;
  const float *cls = nullptr, *boxp = nullptr, *anc = nullptr, *gtb = nullptr;
  for (int i = 0; i < n_in; ++i) {
    switch (in_sizes[i]) {
      case 294912:  cls  = (const float*)d_in[i]; break;  // [8,9,64,64]
      case 1179648: boxp = (const float*)d_in[i]; break;  // [8,36,64,64]
      case 147456:  anc  = (const float*)d_in[i]; break;  // [36864,4]
      case 4096:    gtb  = (const float*)d_in[i]; break;  // [8,128,4]
    }
  }
  float* out = (float*)d_out;

  // host-side key ladder: key(42)=(0,42); img[b]=tf(root,0,b); k1=tf(img,0,0); k2=tf(img,0,1)
  Keys keys;
  for (int b = 0; b < NB; ++b) {
    unsigned i0, i1, a0, a1, b0, b1;
    tf2x32(0u, 42u, 0u, (unsigned)b, i0, i1);
    tf2x32(i0, i1, 0u, 0u, a0, a1);
    tf2x32(i0, i1, 0u, 1u, b0, b1);
    keys.k[4 * b + 0] = a0; keys.k[4 * b + 1] = a1;
    keys.k[4 * b + 2] = b0; keys.k[4 * b + 3] = b1;
  }

  k_row<<<dim3(144, 8), 256>>>(anc, gtb, keys);
  k_col<<<dim3(16, 8, 4), 256>>>(anc, gtb);
  k_sample<<<NB, 1024, NA + 2048 * 4>>>(cls, boxp, anc, gtb);
  k_final<<<1, 32>>>(out);
}

// round 14
// speedup vs baseline: 1.5050x; 1.5050x over previous
#include <cuda_runtime.h>

#define NB 8
#define NK 9
#define NA 36864
#define NG 128
#define BA (NB*NA)
#define IT 36            // NA / 1024 anchors per thread in k_sample
#define LISTCAP 512

struct Keys { unsigned k[32]; }; // per image b: [4b]=k1.lo0,[4b+1]=k1.lo1,[4b+2]=k2.lo0,[4b+3]=k2.lo1

// ------------- scratch: static device globals (no allocation) -------------
__device__ float              g_maxiou[BA];
__device__ int                g_mgt[BA];
__device__ unsigned           g_sp[BA];
__device__ unsigned           g_sn[BA];
__device__ unsigned long long g_colmax[NB * NG]; // zero at module load; k_sample re-zeroes after use
__device__ float              g_loss[NB * 2];

// ------------- threefry2x32, bit-exact JAX replica (verified rel_err=0) -------------
__host__ __device__ __forceinline__ void tf2x32(unsigned k0, unsigned k1,
                                                unsigned x0, unsigned x1,
                                                unsigned &o0, unsigned &o1) {
  unsigned k2 = k0 ^ k1 ^ 0x1BD11BDAu;
  x0 += k0; x1 += k1;
#define TFR(r) { x0 += x1; x1 = (x1 << (r)) | (x1 >> (32 - (r))); x1 ^= x0; }
  TFR(13) TFR(15) TFR(26) TFR(6)
  x0 += k1; x1 += k2 + 1u;
  TFR(17) TFR(29) TFR(16) TFR(24)
  x0 += k2; x1 += k0 + 2u;
  TFR(13) TFR(15) TFR(26) TFR(6)
  x0 += k0; x1 += k1 + 3u;
  TFR(17) TFR(29) TFR(16) TFR(24)
  x0 += k1; x1 += k2 + 4u;
  TFR(13) TFR(15) TFR(26) TFR(6)
  x0 += k2; x1 += k0 + 5u;
#undef TFR
  o0 = x0; o1 = x1;
}

// ------------- IoU in XLA's exact op order (no FMA contraction) -------------
__device__ __forceinline__ float iou_fn(float4 A, float aa, float4 G, float ag) {
  float ltx = fmaxf(A.x, G.x), lty = fmaxf(A.y, G.y);
  float rbx = fminf(A.z, G.z), rby = fminf(A.w, G.w);
  float wx = fmaxf(__fsub_rn(rbx, ltx), 0.0f);
  float wy = fmaxf(__fsub_rn(rby, lty), 0.0f);
  float inter = __fmul_rn(wx, wy);
  float den = __fadd_rn(__fsub_rn(__fadd_rn(aa, ag), inter), 1e-6f);
  return __fdiv_rn(inter, den);
}

// ------------- K1 (fused): row max/argmax + column max + priority streams -------------
// grid (72, 8) x 256 threads; 2 anchors per thread.
__global__ void __launch_bounds__(256) k_row(const float4* __restrict__ anchors,
                                             const float4* __restrict__ gt, Keys keys) {
  __shared__ float4 sg[NG];
  __shared__ float sarea[NG];
  __shared__ unsigned long long scol[NG];
  int b = blockIdx.y;
  int tid = threadIdx.x;
  if (tid < NG) {
    float4 G = gt[b * NG + tid];
    sg[tid] = G;
    sarea[tid] = __fmul_rn(__fsub_rn(G.z, G.x), __fsub_rn(G.w, G.y));
    scol[tid] = 0ull;
  }
  __syncthreads();
  int a0 = blockIdx.x * 512 + tid;
  int a1 = a0 + 256;
  float4 A0 = anchors[a0], A1 = anchors[a1];
  float aa0 = __fmul_rn(__fsub_rn(A0.z, A0.x), __fsub_rn(A0.w, A0.y));
  float aa1 = __fmul_rn(__fsub_rn(A1.z, A1.x), __fsub_rn(A1.w, A1.y));
  float best0 = -1.0f, best1 = -1.0f;
  int bi0 = 0, bi1 = 0;
  int lane = tid & 31;
#pragma unroll 4
  for (int g = 0; g < NG; ++g) {
    float4 G = sg[g];
    float ag = sarea[g];
    float v0 = iou_fn(A0, aa0, G, ag);
    float v1 = iou_fn(A1, aa1, G, ag);
    if (v0 > best0) { best0 = v0; bi0 = g; }   // first-max == jnp.argmax(axis=1)
    if (v1 > best1) { best1 = v1; bi1 = g; }
    unsigned u0 = __float_as_uint(v0), u1 = __float_as_uint(v1);
    // skip column reduction if ALL 64 warp anchors have iou==0 for this gt:
    // every gt's global max iou is > 0, so zero keys can never win.
    if (__ballot_sync(0xffffffffu, (u0 | u1) != 0u)) {
      unsigned long long k0 = ((unsigned long long)u0 << 32) |
                              (unsigned long long)(0xFFFFFFFFu - (unsigned)a0);
      unsigned long long k1 = ((unsigned long long)u1 << 32) |
                              (unsigned long long)(0xFFFFFFFFu - (unsigned)a1);
      unsigned long long key = (k1 > k0) ? k1 : k0;   // max iou; tie -> smaller anchor
      for (int o = 16; o; o >>= 1) {
        unsigned long long t = __shfl_down_sync(0xffffffffu, key, o);
        if (t > key) key = t;
      }
      if (lane == 0) atomicMax(&scol[g], key);
    }
  }
  int off0 = b * NA + a0, off1 = b * NA + a1;
  g_maxiou[off0] = best0; g_maxiou[off1] = best1;
  g_mgt[off0] = bi0;      g_mgt[off1] = bi1;
  unsigned o0, o1;
  tf2x32(keys.k[4 * b + 0], keys.k[4 * b + 1], 0u, (unsigned)a0, o0, o1);
  g_sp[off0] = (o0 ^ o1) >> 9;                 // 23-bit uniform-order priority
  tf2x32(keys.k[4 * b + 0], keys.k[4 * b + 1], 0u, (unsigned)a1, o0, o1);
  g_sp[off1] = (o0 ^ o1) >> 9;
  tf2x32(keys.k[4 * b + 2], keys.k[4 * b + 3], 0u, (unsigned)a0, o0, o1);
  g_sn[off0] = (o0 ^ o1) >> 9;
  tf2x32(keys.k[4 * b + 2], keys.k[4 * b + 3], 0u, (unsigned)a1, o0, o1);
  g_sn[off1] = (o0 ^ o1) >> 9;
  __syncthreads();
  if (tid < NG && scol[tid] != 0ull)
    atomicMax(&g_colmax[b * NG + tid], scol[tid]);
}

// ------------- block reductions (1024 threads) -------------
__device__ __forceinline__ int blkSumI(int v, int* sred) {
  int l = threadIdx.x & 31, w = threadIdx.x >> 5;
  for (int o = 16; o; o >>= 1) v += __shfl_down_sync(0xffffffffu, v, o);
  if (l == 0) sred[w] = v;
  __syncthreads();
  if (w == 0) {
    int t = sred[l];
    for (int o = 16; o; o >>= 1) t += __shfl_down_sync(0xffffffffu, t, o);
    if (l == 0) sred[0] = t;
  }
  __syncthreads();
  int r = sred[0];
  __syncthreads();
  return r;
}

__device__ __forceinline__ float blkSumF(float v, float* sred) {
  int l = threadIdx.x & 31, w = threadIdx.x >> 5;
  for (int o = 16; o; o >>= 1) v += __shfl_down_sync(0xffffffffu, v, o);
  if (l == 0) sred[w] = v;
  __syncthreads();
  if (w == 0) {
    float t = sred[l];
    for (int o = 16; o; o >>= 1) t += __shfl_down_sync(0xffffffffu, t, o);
    if (l == 0) sred[0] = t;
  }
  __syncthreads();
  float r = sred[0];
  __syncthreads();
  return r;
}

// ------------- exact top-k selection with stable-argsort tie semantics -------------
// `list` ALIASES `hist` (hist is dead once sScal[0..1] are set); dyn smem 45056 B.
__device__ void selectTopK(signed char* lab, unsigned* hist,
                           const unsigned* __restrict__ prio, int b, int k, int count,
                           int want, unsigned* warpSum, int* sScal) {
  int tid = threadIdx.x;
  unsigned long long* list = (unsigned long long*)hist;   // alias, used after hist is dead
  if (k >= count) return;                       // keep all masked
  if (k <= 0) {                                 // demote all masked
    for (int i = 0; i < IT; ++i) {
      int a = i * 1024 + tid;
      if (lab[a] == want) lab[a] = -1;
    }
    __syncthreads();
    return;
  }
  // pass 1: histogram over top 11 bits of the 23-bit priority
  for (int j = tid; j < 2048; j += 1024) hist[j] = 0u;
  if (tid == 0) sScal[2] = 0;
  __syncthreads();
  for (int i = 0; i < IT; ++i) {
    int a = i * 1024 + tid;
    if (lab[a] == want) atomicAdd(&hist[prio[b * NA + a] >> 12], 1u);
  }
  __syncthreads();
  {
    int w = tid >> 5, l = tid & 31;
    unsigned s = hist[w * 64 + l] + hist[w * 64 + l + 32];
    for (int o = 16; o; o >>= 1) s += __shfl_down_sync(0xffffffffu, s, o);
    if (l == 0) warpSum[w] = s;
  }
  __syncthreads();
  if (tid == 0) {
    int acc = 0, C = 0;
    for (int w = 31; w >= 0; --w) {
      if (acc + (int)warpSum[w] >= k) { C = w; break; }
      acc += (int)warpSum[w];
    }
    int B = C * 64;
    for (int bin = C * 64 + 63; bin >= C * 64; --bin) {
      if (acc + (int)hist[bin] >= k) { B = bin; break; }
      acc += (int)hist[bin];
    }
    sScal[0] = B; sScal[1] = acc;               // acc = count strictly above bucket B
  }
  __syncthreads();
  int B = sScal[0], above = sScal[1], r = k - above;  // 1 <= r <= hist[B]
  // hist is dead from here on; list overwrites it.
  for (int i = 0; i < IT; ++i) {
    int a = i * 1024 + tid;
    if (lab[a] == want) {
      unsigned p = prio[b * NA + a];
      int bkt = (int)(p >> 12);
      if (bkt < B) {
        lab[a] = -1;                            // below threshold bucket: demote
      } else if (bkt == B) {
        int pos = atomicAdd(&sScal[2], 1);
        if (pos < LISTCAP)
          list[pos] = ((unsigned long long)p << 32) |
                      (unsigned long long)(0xFFFFFFFFu - (unsigned)a);
      }
    }
  }
  __syncthreads();
  int m = sScal[2]; if (m > LISTCAP) m = LISTCAP;
  for (int e = tid; e < m; e += 1024) {
    unsigned long long K = list[e];
    int rank = 0;
    for (int j = 0; j < m; ++j) rank += (list[j] > K);  // value desc, index asc (keys unique)
    if (rank >= r) {
      unsigned a = 0xFFFFFFFFu - (unsigned)(K & 0xFFFFFFFFull);
      lab[a] = -1;
    }
  }
  __syncthreads();
}

// ------------- K2: per-image labels, sampling, losses -------------
// dynamic shared: lab 36864 B + hist 8192 B = 45056 B (< 48 KB, no opt-in needed)
__global__ void __launch_bounds__(1024) k_sample(const float* __restrict__ cls,
                                                 const float* __restrict__ boxp,
                                                 const float* __restrict__ anchors,
                                                 const float* __restrict__ gt) {
  extern __shared__ unsigned char smem[];
  signed char* lab = (signed char*)smem;                                // 36864 B
  unsigned* hist = (unsigned*)(smem + NA);                              // 8192 B (list aliases)
  __shared__ int sredI[32];
  __shared__ float sredF[32];
  __shared__ unsigned warpSum[32];
  __shared__ int sScal[3];
  int b = blockIdx.x, tid = threadIdx.x;

  // base labels
  for (int i = 0; i < IT; ++i) {
    int a = i * 1024 + tid;
    float mi = g_maxiou[b * NA + a];
    lab[a] = (mi >= 0.7f) ? 1 : ((mi < 0.3f) ? 0 : -1);
  }
  __syncthreads();
  // forced positives (best anchor per gt)
  if (tid < NG) {
    unsigned long long key = g_colmax[b * NG + tid];
    unsigned a = 0xFFFFFFFFu - (unsigned)(key & 0xFFFFFFFFull);
    if (a < NA) lab[a] = 1;
  }
  __syncthreads();
  // reset colmax for the next graph replay (stream-ordered before next k_row)
  if (tid < NG) g_colmax[b * NG + tid] = 0ull;

  int myPos = 0, myNeg = 0;
  for (int i = 0; i < IT; ++i) {
    int l = lab[i * 1024 + tid];
    myPos += (l == 1); myNeg += (l == 0);
  }
  int numPos = blkSumI(myPos, sredI);
  int numNeg = blkSumI(myNeg, sredI);
  int targetPos = min(128, numPos);
  selectTopK(lab, hist, g_sp, b, targetPos, numPos, 1, warpSum, sScal);
  int targetNeg = min(256 - targetPos, numNeg);
  selectTopK(lab, hist, g_sn, b, targetNeg, numNeg, 0, warpSum, sScal);

  // losses over sampled (<=256) anchors
  float clsSum = 0.f, boxSum = 0.f;
  int vcnt = 0, pcnt = 0;
  for (int i = 0; i < IT; ++i) {
    int a = i * 1024 + tid;
    int l = lab[a];
    if (l >= 0) {
      int j = a % NK, pix = a / NK;
      float x = cls[(b * NK + j) * 4096 + pix];
      float bce = fmaxf(x, 0.f) + log1pf(expf(-fabsf(x)));
      if (l == 1) bce -= x;
      clsSum += bce; ++vcnt;
      if (l == 1) {
        ++pcnt;
        int g = g_mgt[b * NA + a];
        float4 A = reinterpret_cast<const float4*>(anchors)[a];
        float4 G = reinterpret_cast<const float4*>(gt)[b * NG + g];
        float aw = A.z - A.x, ah = A.w - A.y;
        float acx = (A.x + A.z) * 0.5f, acy = (A.y + A.w) * 0.5f;
        float gw = G.z - G.x, gh = G.w - G.y;
        float gcx = (G.x + G.z) * 0.5f, gcy = (G.y + G.w) * 0.5f;
        float t[4] = {(gcx - acx) / aw, (gcy - acy) / ah, logf(gw / aw), logf(gh / ah)};
        int base = (b * 36 + 4 * j) * 4096 + pix;
#pragma unroll
        for (int c = 0; c < 4; ++c) {
          float d = boxp[base + c * 4096] - t[c];
          float ad = fabsf(d);
          boxSum += (ad < 1.f) ? 0.5f * d * d : ad - 0.5f;
        }
      }
    }
  }
  clsSum = blkSumF(clsSum, sredF);
  vcnt = blkSumI(vcnt, sredI);
  boxSum = blkSumF(boxSum, sredF);
  pcnt = blkSumI(pcnt, sredI);
  if (tid == 0) {
    g_loss[b * 2] = clsSum / fmaxf((float)vcnt, 1.f);
    g_loss[b * 2 + 1] = boxSum / fmaxf(4.f * (float)pcnt, 1.f);
  }
}

// ------------- K3: means -------------
__global__ void k_final(float* __restrict__ out) {
  if (threadIdx.x == 0) {
    float cs = 0.f, bs = 0.f;
    for (int b = 0; b < NB; ++b) { cs += g_loss[2 * b]; bs += g_loss[2 * b + 1]; }
    cs *= 0.125f; bs *= 0.125f;
    out[0] = cs; out[1] = bs; out[2] = cs + bs;
  }
}

extern "C" void kernel_launch(void* const* d_in, const int* in_sizes, int n_in,
                              void* d_out, int out_size) {
  (void)out_size;
  const float *cls = nullptr, *boxp = nullptr, *anc = nullptr, *gtb = nullptr;
  for (int i = 0; i < n_in; ++i) {
    switch (in_sizes[i]) {
      case 294912:  cls  = (const float*)d_in[i]; break;  // [8,9,64,64]
      case 1179648: boxp = (const float*)d_in[i]; break;  // [8,36,64,64]
      case 147456:  anc  = (const float*)d_in[i]; break;  // [36864,4]
      case 4096:    gtb  = (const float*)d_in[i]; break;  // [8,128,4]
    }
  }
  float* out = (float*)d_out;

  // host-side key ladder: key(42)=(0,42); img[b]=tf(root,0,b); k1=tf(img,0,0); k2=tf(img,0,1)
  Keys keys;
  for (int b = 0; b < NB; ++b) {
    unsigned i0, i1, a0, a1, b0, b1;
    tf2x32(0u, 42u, 0u, (unsigned)b, i0, i1);
    tf2x32(i0, i1, 0u, 0u, a0, a1);
    tf2x32(i0, i1, 0u, 1u, b0, b1);
    keys.k[4 * b + 0] = a0; keys.k[4 * b + 1] = a1;
    keys.k[4 * b + 2] = b0; keys.k[4 * b + 3] = b1;
  }

  k_row<<<dim3(72, 8), 256>>>((const float4*)anc, (const float4*)gtb, keys);
  k_sample<<<NB, 1024, NA + 2048 * 4>>>(cls, boxp, anc, gtb);
  k_final<<<1, 32>>>(out);
}

// round 15
// speedup vs baseline: 2.4551x; 1.6313x over previous
#include <cuda_runtime.h>

#define NB 8
#define NK 9
#define NA 36864
#define NG 128
#define BA (NB*NA)
#define IT 36            // NA / 1024 anchors per thread in k_sample
#define LISTCAP 512

struct Keys { unsigned k[32]; }; // per image b: [4b]=k1.lo0,[4b+1]=k1.lo1,[4b+2]=k2.lo0,[4b+3]=k2.lo1

// ------------- scratch: static device globals (no allocation) -------------
__device__ float              g_maxiou[BA];
__device__ int                g_mgt[BA];
__device__ unsigned           g_sp[BA];
__device__ unsigned           g_sn[BA];
__device__ unsigned long long g_colmax[NB * NG]; // zero at module load; k_sample re-zeroes after use
__device__ float              g_loss[NB * 2];

// ------------- threefry2x32, bit-exact JAX replica (verified rel_err=0) -------------
__host__ __device__ __forceinline__ void tf2x32(unsigned k0, unsigned k1,
                                                unsigned x0, unsigned x1,
                                                unsigned &o0, unsigned &o1) {
  unsigned k2 = k0 ^ k1 ^ 0x1BD11BDAu;
  x0 += k0; x1 += k1;
#define TFR(r) { x0 += x1; x1 = (x1 << (r)) | (x1 >> (32 - (r))); x1 ^= x0; }
  TFR(13) TFR(15) TFR(26) TFR(6)
  x0 += k1; x1 += k2 + 1u;
  TFR(17) TFR(29) TFR(16) TFR(24)
  x0 += k2; x1 += k0 + 2u;
  TFR(13) TFR(15) TFR(26) TFR(6)
  x0 += k0; x1 += k1 + 3u;
  TFR(17) TFR(29) TFR(16) TFR(24)
  x0 += k1; x1 += k2 + 4u;
  TFR(13) TFR(15) TFR(26) TFR(6)
  x0 += k2; x1 += k0 + 5u;
#undef TFR
  o0 = x0; o1 = x1;
}

// ------------- K1 (fused): row max/argmax + column max + priority streams -------------
// grid (72, 8) x 256 threads; 2 anchors per thread.
// Sparsity-aware: only ~7% of anchor-gt pairs overlap. Compute `inter` always
// (9 ops); the div/den/compare/column-candidate run only for nonzero lanes.
// Bit-exactness: inter==0 -> iou = +0/den = +0 exactly; best init (0.0f, 0)
// reproduces jnp.argmax (strict > keeps first max; all-zero row -> index 0);
// zero keys never win the per-gt column argmax (every gt's max iou > 0).
__global__ void __launch_bounds__(256) k_row(const float4* __restrict__ anchors,
                                             const float4* __restrict__ gt, Keys keys) {
  __shared__ float4 sg[NG];
  __shared__ float sarea[NG];
  __shared__ unsigned long long scol[NG];
  int b = blockIdx.y;
  int tid = threadIdx.x;
  if (tid < NG) {
    float4 G = gt[b * NG + tid];
    sg[tid] = G;
    sarea[tid] = __fmul_rn(__fsub_rn(G.z, G.x), __fsub_rn(G.w, G.y));
    scol[tid] = 0ull;
  }
  __syncthreads();
  int a0 = blockIdx.x * 512 + tid;
  int a1 = a0 + 256;
  float4 A0 = anchors[a0], A1 = anchors[a1];
  float aa0 = __fmul_rn(__fsub_rn(A0.z, A0.x), __fsub_rn(A0.w, A0.y));
  float aa1 = __fmul_rn(__fsub_rn(A1.z, A1.x), __fsub_rn(A1.w, A1.y));
  float best0 = 0.0f, best1 = 0.0f;   // iou >= 0 always; matches argmax semantics
  int bi0 = 0, bi1 = 0;
  unsigned long long inv0 = (unsigned long long)(0xFFFFFFFFu - (unsigned)a0);
  unsigned long long inv1 = (unsigned long long)(0xFFFFFFFFu - (unsigned)a1);
#pragma unroll 4
  for (int g = 0; g < NG; ++g) {
    float4 G = sg[g];
    float ag = sarea[g];
    // intersection areas (XLA op order, no FMA contraction)
    float wx0 = fmaxf(__fsub_rn(fminf(A0.z, G.z), fmaxf(A0.x, G.x)), 0.0f);
    float wy0 = fmaxf(__fsub_rn(fminf(A0.w, G.w), fmaxf(A0.y, G.y)), 0.0f);
    float inter0 = __fmul_rn(wx0, wy0);
    float wx1 = fmaxf(__fsub_rn(fminf(A1.z, G.z), fmaxf(A1.x, G.x)), 0.0f);
    float wy1 = fmaxf(__fsub_rn(fminf(A1.w, G.w), fmaxf(A1.y, G.y)), 0.0f);
    float inter1 = __fmul_rn(wx1, wy1);
    if (inter0 != 0.0f) {
      float den = __fadd_rn(__fsub_rn(__fadd_rn(aa0, ag), inter0), 1e-6f);
      float v = __fdiv_rn(inter0, den);
      if (v > best0) { best0 = v; bi0 = g; }
      atomicMax(&scol[g], ((unsigned long long)__float_as_uint(v) << 32) | inv0);
    }
    if (inter1 != 0.0f) {
      float den = __fadd_rn(__fsub_rn(__fadd_rn(aa1, ag), inter1), 1e-6f);
      float v = __fdiv_rn(inter1, den);
      if (v > best1) { best1 = v; bi1 = g; }
      atomicMax(&scol[g], ((unsigned long long)__float_as_uint(v) << 32) | inv1);
    }
  }
  int off0 = b * NA + a0, off1 = b * NA + a1;
  g_maxiou[off0] = best0; g_maxiou[off1] = best1;
  g_mgt[off0] = bi0;      g_mgt[off1] = bi1;
  unsigned o0, o1;
  tf2x32(keys.k[4 * b + 0], keys.k[4 * b + 1], 0u, (unsigned)a0, o0, o1);
  g_sp[off0] = (o0 ^ o1) >> 9;                 // 23-bit uniform-order priority
  tf2x32(keys.k[4 * b + 0], keys.k[4 * b + 1], 0u, (unsigned)a1, o0, o1);
  g_sp[off1] = (o0 ^ o1) >> 9;
  tf2x32(keys.k[4 * b + 2], keys.k[4 * b + 3], 0u, (unsigned)a0, o0, o1);
  g_sn[off0] = (o0 ^ o1) >> 9;
  tf2x32(keys.k[4 * b + 2], keys.k[4 * b + 3], 0u, (unsigned)a1, o0, o1);
  g_sn[off1] = (o0 ^ o1) >> 9;
  __syncthreads();
  if (tid < NG && scol[tid] != 0ull)
    atomicMax(&g_colmax[b * NG + tid], scol[tid]);
}

// ------------- block reductions (1024 threads) -------------
__device__ __forceinline__ int blkSumI(int v, int* sred) {
  int l = threadIdx.x & 31, w = threadIdx.x >> 5;
  for (int o = 16; o; o >>= 1) v += __shfl_down_sync(0xffffffffu, v, o);
  if (l == 0) sred[w] = v;
  __syncthreads();
  if (w == 0) {
    int t = sred[l];
    for (int o = 16; o; o >>= 1) t += __shfl_down_sync(0xffffffffu, t, o);
    if (l == 0) sred[0] = t;
  }
  __syncthreads();
  int r = sred[0];
  __syncthreads();
  return r;
}

__device__ __forceinline__ float blkSumF(float v, float* sred) {
  int l = threadIdx.x & 31, w = threadIdx.x >> 5;
  for (int o = 16; o; o >>= 1) v += __shfl_down_sync(0xffffffffu, v, o);
  if (l == 0) sred[w] = v;
  __syncthreads();
  if (w == 0) {
    float t = sred[l];
    for (int o = 16; o; o >>= 1) t += __shfl_down_sync(0xffffffffu, t, o);
    if (l == 0) sred[0] = t;
  }
  __syncthreads();
  float r = sred[0];
  __syncthreads();
  return r;
}

// ------------- exact top-k selection with stable-argsort tie semantics -------------
// `list` ALIASES `hist` (hist is dead once sScal[0..1] are set); dyn smem 45056 B.
__device__ void selectTopK(signed char* lab, unsigned* hist,
                           const unsigned* __restrict__ prio, int b, int k, int count,
                           int want, unsigned* warpSum, int* sScal) {
  int tid = threadIdx.x;
  unsigned long long* list = (unsigned long long*)hist;   // alias, used after hist is dead
  if (k >= count) return;                       // keep all masked
  if (k <= 0) {                                 // demote all masked
    for (int i = 0; i < IT; ++i) {
      int a = i * 1024 + tid;
      if (lab[a] == want) lab[a] = -1;
    }
    __syncthreads();
    return;
  }
  // pass 1: histogram over top 11 bits of the 23-bit priority
  for (int j = tid; j < 2048; j += 1024) hist[j] = 0u;
  if (tid == 0) sScal[2] = 0;
  __syncthreads();
  for (int i = 0; i < IT; ++i) {
    int a = i * 1024 + tid;
    if (lab[a] == want) atomicAdd(&hist[prio[b * NA + a] >> 12], 1u);
  }
  __syncthreads();
  {
    int w = tid >> 5, l = tid & 31;
    unsigned s = hist[w * 64 + l] + hist[w * 64 + l + 32];
    for (int o = 16; o; o >>= 1) s += __shfl_down_sync(0xffffffffu, s, o);
    if (l == 0) warpSum[w] = s;
  }
  __syncthreads();
  if (tid == 0) {
    int acc = 0, C = 0;
    for (int w = 31; w >= 0; --w) {
      if (acc + (int)warpSum[w] >= k) { C = w; break; }
      acc += (int)warpSum[w];
    }
    int B = C * 64;
    for (int bin = C * 64 + 63; bin >= C * 64; --bin) {
      if (acc + (int)hist[bin] >= k) { B = bin; break; }
      acc += (int)hist[bin];
    }
    sScal[0] = B; sScal[1] = acc;               // acc = count strictly above bucket B
  }
  __syncthreads();
  int B = sScal[0], above = sScal[1], r = k - above;  // 1 <= r <= hist[B]
  // hist is dead from here on; list overwrites it.
  for (int i = 0; i < IT; ++i) {
    int a = i * 1024 + tid;
    if (lab[a] == want) {
      unsigned p = prio[b * NA + a];
      int bkt = (int)(p >> 12);
      if (bkt < B) {
        lab[a] = -1;                            // below threshold bucket: demote
      } else if (bkt == B) {
        int pos = atomicAdd(&sScal[2], 1);
        if (pos < LISTCAP)
          list[pos] = ((unsigned long long)p << 32) |
                      (unsigned long long)(0xFFFFFFFFu - (unsigned)a);
      }
    }
  }
  __syncthreads();
  int m = sScal[2]; if (m > LISTCAP) m = LISTCAP;
  for (int e = tid; e < m; e += 1024) {
    unsigned long long K = list[e];
    int rank = 0;
    for (int j = 0; j < m; ++j) rank += (list[j] > K);  // value desc, index asc (keys unique)
    if (rank >= r) {
      unsigned a = 0xFFFFFFFFu - (unsigned)(K & 0xFFFFFFFFull);
      lab[a] = -1;
    }
  }
  __syncthreads();
}

// ------------- K2: per-image labels, sampling, losses -------------
// dynamic shared: lab 36864 B + hist 8192 B = 45056 B (< 48 KB, no opt-in needed)
__global__ void __launch_bounds__(1024) k_sample(const float* __restrict__ cls,
                                                 const float* __restrict__ boxp,
                                                 const float* __restrict__ anchors,
                                                 const float* __restrict__ gt) {
  extern __shared__ unsigned char smem[];
  signed char* lab = (signed char*)smem;                                // 36864 B
  unsigned* hist = (unsigned*)(smem + NA);                              // 8192 B (list aliases)
  __shared__ int sredI[32];
  __shared__ float sredF[32];
  __shared__ unsigned warpSum[32];
  __shared__ int sScal[3];
  int b = blockIdx.x, tid = threadIdx.x;

  // base labels
  for (int i = 0; i < IT; ++i) {
    int a = i * 1024 + tid;
    float mi = g_maxiou[b * NA + a];
    lab[a] = (mi >= 0.7f) ? 1 : ((mi < 0.3f) ? 0 : -1);
  }
  __syncthreads();
  // forced positives (best anchor per gt)
  if (tid < NG) {
    unsigned long long key = g_colmax[b * NG + tid];
    unsigned a = 0xFFFFFFFFu - (unsigned)(key & 0xFFFFFFFFull);
    if (a < NA) lab[a] = 1;
  }
  __syncthreads();
  // reset colmax for the next graph replay (stream-ordered before next k_row)
  if (tid < NG) g_colmax[b * NG + tid] = 0ull;

  int myPos = 0, myNeg = 0;
  for (int i = 0; i < IT; ++i) {
    int l = lab[i * 1024 + tid];
    myPos += (l == 1); myNeg += (l == 0);
  }
  int numPos = blkSumI(myPos, sredI);
  int numNeg = blkSumI(myNeg, sredI);
  int targetPos = min(128, numPos);
  selectTopK(lab, hist, g_sp, b, targetPos, numPos, 1, warpSum, sScal);
  int targetNeg = min(256 - targetPos, numNeg);
  selectTopK(lab, hist, g_sn, b, targetNeg, numNeg, 0, warpSum, sScal);

  // losses over sampled (<=256) anchors
  float clsSum = 0.f, boxSum = 0.f;
  int vcnt = 0, pcnt = 0;
  for (int i = 0; i < IT; ++i) {
    int a = i * 1024 + tid;
    int l = lab[a];
    if (l >= 0) {
      int j = a % NK, pix = a / NK;
      float x = cls[(b * NK + j) * 4096 + pix];
      float bce = fmaxf(x, 0.f) + log1pf(expf(-fabsf(x)));
      if (l == 1) bce -= x;
      clsSum += bce; ++vcnt;
      if (l == 1) {
        ++pcnt;
        int g = g_mgt[b * NA + a];
        float4 A = reinterpret_cast<const float4*>(anchors)[a];
        float4 G = reinterpret_cast<const float4*>(gt)[b * NG + g];
        float aw = A.z - A.x, ah = A.w - A.y;
        float acx = (A.x + A.z) * 0.5f, acy = (A.y + A.w) * 0.5f;
        float gw = G.z - G.x, gh = G.w - G.y;
        float gcx = (G.x + G.z) * 0.5f, gcy = (G.y + G.w) * 0.5f;
        float t[4] = {(gcx - acx) / aw, (gcy - acy) / ah, logf(gw / aw), logf(gh / ah)};
        int base = (b * 36 + 4 * j) * 4096 + pix;
#pragma unroll
        for (int c = 0; c < 4; ++c) {
          float d = boxp[base + c * 4096] - t[c];
          float ad = fabsf(d);
          boxSum += (ad < 1.f) ? 0.5f * d * d : ad - 0.5f;
        }
      }
    }
  }
  clsSum = blkSumF(clsSum, sredF);
  vcnt = blkSumI(vcnt, sredI);
  boxSum = blkSumF(boxSum, sredF);
  pcnt = blkSumI(pcnt, sredI);
  if (tid == 0) {
    g_loss[b * 2] = clsSum / fmaxf((float)vcnt, 1.f);
    g_loss[b * 2 + 1] = boxSum / fmaxf(4.f * (float)pcnt, 1.f);
  }
}

// ------------- K3: means -------------
__global__ void k_final(float* __restrict__ out) {
  if (threadIdx.x == 0) {
    float cs = 0.f, bs = 0.f;
    for (int b = 0; b < NB; ++b) { cs += g_loss[2 * b]; bs += g_loss[2 * b + 1]; }
    cs *= 0.125f; bs *= 0.125f;
    out[0] = cs; out[1] = bs; out[2] = cs + bs;
  }
}

extern "C" void kernel_launch(void* const* d_in, const int* in_sizes, int n_in,
                              void* d_out, int out_size) {
  (void)out_size;
  const float *cls = nullptr, *boxp = nullptr, *anc = nullptr, *gtb = nullptr;
  for (int i = 0; i < n_in; ++i) {
    switch (in_sizes[i]) {
      case 294912:  cls  = (const float*)d_in[i]; break;  // [8,9,64,64]
      case 1179648: boxp = (const float*)d_in[i]; break;  // [8,36,64,64]
      case 147456:  anc  = (const float*)d_in[i]; break;  // [36864,4]
      case 4096:    gtb  = (const float*)d_in[i]; break;  // [8,128,4]
    }
  }
  float* out = (float*)d_out;

  // host-side key ladder: key(42)=(0,42); img[b]=tf(root,0,b); k1=tf(img,0,0); k2=tf(img,0,1)
  Keys keys;
  for (int b = 0; b < NB; ++b) {
    unsigned i0, i1, a0, a1, b0, b1;
    tf2x32(0u, 42u, 0u, (unsigned)b, i0, i1);
    tf2x32(i0, i1, 0u, 0u, a0, a1);
    tf2x32(i0, i1, 0u, 1u, b0, b1);
    keys.k[4 * b + 0] = a0; keys.k[4 * b + 1] = a1;
    keys.k[4 * b + 2] = b0; keys.k[4 * b + 3] = b1;
  }

  k_row<<<dim3(72, 8), 256>>>((const float4*)anc, (const float4*)gtb, keys);
  k_sample<<<NB, 1024, NA + 2048 * 4>>>(cls, boxp, anc, gtb);
  k_final<<<1, 32>>>(out);
}